// round 5
// baseline (speedup 1.0000x reference)
#include <cuda_runtime.h>

#define TPB   256
#define CHUNK 2048          // candidate tile: 2048 * 16B = 32 KB smem

// ---------------- scratch (static __device__ — no allocation) ----------------
__device__ float4             g_gt4[32768];   // gt points  + |g|^2 in .w
__device__ float4             g_pr4[8192];    // pred points + |p|^2 in .w
__device__ unsigned long long g_best1[8192];  // per pred:  (key<<32)|gt_idx
__device__ unsigned long long g_best2[32768]; // per gt:    (key<<32)|pred_idx
__device__ float              g_partial[128]; // [0..64) sum dot1, [64..128) sum dot2

// ---------------- prep: pack float4 with squared norm, init winners ----------
__global__ void prep_kernel(const float* __restrict__ pp,
                            const float* __restrict__ gp, int N, int M) {
    int i = blockIdx.x * blockDim.x + threadIdx.x;
    if (i < N) {
        float x = pp[3 * i], y = pp[3 * i + 1], z = pp[3 * i + 2];
        g_pr4[i] = make_float4(x, y, z, x * x + y * y + z * z);
        g_best1[i] = ~0ULL;
    }
    if (i < M) {
        float x = gp[3 * i], y = gp[3 * i + 1], z = gp[3 * i + 2];
        g_gt4[i] = make_float4(x, y, z, x * x + y * y + z * z);
        g_best2[i] = ~0ULL;
    }
}

// monotone float -> uint mapping (handles negative scores; score = d2 - |q|^2)
__device__ __forceinline__ unsigned fkey(float f) {
    unsigned u = __float_as_uint(f);
    return u ^ ((u & 0x80000000u) ? 0xFFFFFFFFu : 0x80000000u);
}

// ---------------- split-candidate brute-force argmin -------------------------
// DIR==0: queries = pred (NQ=N), candidates = gt  (NC=M) -> g_best1
// DIR==1: queries = gt   (NQ=M), candidates = pred(NC=N) -> g_best2
template <int DIR>
__global__ __launch_bounds__(TPB) void argmin_kernel(const float* __restrict__ qpts,
                                                     int NQ, int NC) {
    __shared__ float4 tile[CHUNK];
    const float4* __restrict__ cand = DIR ? g_pr4 : g_gt4;
    unsigned long long* best        = DIR ? g_best2 : g_best1;

    const int base  = blockIdx.y * CHUNK;
    const int count = min(CHUNK, NC - base);
    for (int t = threadIdx.x; t < count; t += TPB) tile[t] = cand[base + t];
    __syncthreads();

    const int qi = blockIdx.x * TPB + threadIdx.x;
    float qx = 0.f, qy = 0.f, qz = 0.f;
    if (qi < NQ) {                 // pre-scale query by -2: score = gg - 2 q.g
        qx = -2.0f * qpts[3 * qi];
        qy = -2.0f * qpts[3 * qi + 1];
        qz = -2.0f * qpts[3 * qi + 2];
    }

    float b0 = 3.4e38f, b1 = 3.4e38f, b2 = 3.4e38f, b3 = 3.4e38f;
    int   i0 = 0, i1 = 0, i2 = 0, i3 = 0;

    int t = 0;
    const int c4 = count & ~3;
    #pragma unroll 2
    for (; t < c4; t += 4) {
        float4 c0 = tile[t], c1 = tile[t + 1], c2 = tile[t + 2], c3 = tile[t + 3];
        float s0 = fmaf(qx, c0.x, fmaf(qy, c0.y, fmaf(qz, c0.z, c0.w)));
        float s1 = fmaf(qx, c1.x, fmaf(qy, c1.y, fmaf(qz, c1.z, c1.w)));
        float s2 = fmaf(qx, c2.x, fmaf(qy, c2.y, fmaf(qz, c2.z, c2.w)));
        float s3 = fmaf(qx, c3.x, fmaf(qy, c3.y, fmaf(qz, c3.z, c3.w)));
        i0 = (s0 < b0) ? (t)     : i0;  b0 = fminf(b0, s0);
        i1 = (s1 < b1) ? (t + 1) : i1;  b1 = fminf(b1, s1);
        i2 = (s2 < b2) ? (t + 2) : i2;  b2 = fminf(b2, s2);
        i3 = (s3 < b3) ? (t + 3) : i3;  b3 = fminf(b3, s3);
    }
    for (; t < count; t++) {
        float4 c = tile[t];
        float  s = fmaf(qx, c.x, fmaf(qy, c.y, fmaf(qz, c.z, c.w)));
        i0 = (s < b0) ? t : i0;  b0 = fminf(b0, s);
    }

    if (qi < NQ) {
        // pack (sortable score, global index): min => smallest score, then
        // smallest index — exactly jnp.argmin's first-occurrence semantics.
        unsigned long long k0 = ((unsigned long long)fkey(b0) << 32) | (unsigned)(base + i0);
        unsigned long long k1 = ((unsigned long long)fkey(b1) << 32) | (unsigned)(base + i1);
        unsigned long long k2 = ((unsigned long long)fkey(b2) << 32) | (unsigned)(base + i2);
        unsigned long long k3 = ((unsigned long long)fkey(b3) << 32) | (unsigned)(base + i3);
        unsigned long long k  = min(min(k0, k1), min(k2, k3));
        atomicMin(&best[qi], k);
    }
}

// ---------------- loss: sum of normal dots (deterministic 2-stage) -----------
__global__ __launch_bounds__(256) void loss_stage1(const float* __restrict__ pn,
                                                   const float* __restrict__ gn,
                                                   int N, int M) {
    const int tid = threadIdx.x;
    const int gid = blockIdx.x * blockDim.x + tid;
    const int stride = gridDim.x * blockDim.x;
    float s1 = 0.f, s2 = 0.f;
    for (int i = gid; i < N; i += stride) {
        int j = (int)(unsigned)g_best1[i];
        s1 += pn[3 * i]     * gn[3 * j]
            + pn[3 * i + 1] * gn[3 * j + 1]
            + pn[3 * i + 2] * gn[3 * j + 2];
    }
    for (int j = gid; j < M; j += stride) {
        int i = (int)(unsigned)g_best2[j];
        s2 += gn[3 * j]     * pn[3 * i]
            + gn[3 * j + 1] * pn[3 * i + 1]
            + gn[3 * j + 2] * pn[3 * i + 2];
    }
    __shared__ float r1[256], r2[256];
    r1[tid] = s1; r2[tid] = s2;
    __syncthreads();
    for (int o = 128; o > 0; o >>= 1) {
        if (tid < o) { r1[tid] += r1[tid + o]; r2[tid] += r2[tid + o]; }
        __syncthreads();
    }
    if (tid == 0) { g_partial[blockIdx.x] = r1[0]; g_partial[64 + blockIdx.x] = r2[0]; }
}

__global__ void finish_kernel(float* __restrict__ out, float invN, float invM) {
    __shared__ float sa[64], sb[64];
    int t = threadIdx.x;
    sa[t] = g_partial[t];
    sb[t] = g_partial[64 + t];
    __syncthreads();
    for (int o = 32; o > 0; o >>= 1) {
        if (t < o) { sa[t] += sa[t + o]; sb[t] += sb[t + o]; }
        __syncthreads();
    }
    // mean(1 - dot1) + mean(1 - dot2) = 2 - sum1/N - sum2/M
    if (t == 0) out[0] = 2.0f - sa[0] * invN - sb[0] * invM;
}

// ---------------- launch -----------------------------------------------------
extern "C" void kernel_launch(void* const* d_in, const int* in_sizes, int n_in,
                              void* d_out, int out_size) {
    const float* pred_pts = (const float*)d_in[0];
    const float* pred_nrm = (const float*)d_in[1];
    const float* gt_pts   = (const float*)d_in[2];
    const float* gt_nrm   = (const float*)d_in[3];
    float* out = (float*)d_out;

    const int N = in_sizes[0] / 3;   // 8192
    const int M = in_sizes[2] / 3;   // 32768
    const int mx = (N > M) ? N : M;

    prep_kernel<<<(mx + TPB - 1) / TPB, TPB>>>(pred_pts, gt_pts, N, M);

    dim3 g1((N + TPB - 1) / TPB, (M + CHUNK - 1) / CHUNK);   // 32 x 16
    argmin_kernel<0><<<g1, TPB>>>(pred_pts, N, M);

    dim3 g2((M + TPB - 1) / TPB, (N + CHUNK - 1) / CHUNK);   // 128 x 4
    argmin_kernel<1><<<g2, TPB>>>(gt_pts, M, N);

    loss_stage1<<<64, 256>>>(pred_nrm, gt_nrm, N, M);
    finish_kernel<<<1, 64>>>(out, 1.0f / (float)N, 1.0f / (float)M);
}